// round 2
// baseline (speedup 1.0000x reference)
#include <cuda_runtime.h>
#include <stdint.h>

// TT config (fixed by the problem)
#define NT 4        // tables
#define P0 100
#define P1C 100
#define P2C 100
#define RNK 32      // r1 == r2 == 32
#define DIM 64      // q0*q1*q2

// Scratch: W12[t][i1][i2][m=q1*4+q2][r1]  (512 floats per (t,i1,i2) slice)
// 4 * 100 * 100 * 512 floats = 81.92 MB, static device global (no allocs).
__device__ float g_W12[(size_t)NT * P1C * P2C * 512];

// ---------------------------------------------------------------------------
// Kernel 1: precompute W12[m][r1] = sum_r2 c1[r1][q1][r2] * c2[r2][q2]
// One block per (t, i1); loops over all i2 so the 16KB c1 slice stays hot in L1.
// ---------------------------------------------------------------------------
__global__ void tt_precompute_kernel(const float* __restrict__ c1g,
                                     const float* __restrict__ c2g) {
    int b = blockIdx.x;                 // 0..399
    int t = b / P1C, i1 = b % P1C;
    const float* c1 = c1g + (size_t)(t * P1C + i1) * 4096;   // [r1][q1][r2]

    __shared__ __align__(16) float c2t[128];                 // [q2][r2] transposed

    int tid = threadIdx.x;              // 256 threads
    int r1  = tid & 31;
    int mA  = tid >> 5;                 // 0..7 ; also handles mB = mA + 8
    int q1A = mA >> 2;                  // 0..1 ; q1B = q1A + 2
    int q2  = mA & 3;                   // same q2 for mA and mB

    const float4* rowA = (const float4*)(c1 + (r1 * 4 + q1A) * 32);
    const float4* rowB = (const float4*)(c1 + (r1 * 4 + q1A + 2) * 32);
    float* Wt = g_W12 + (size_t)(t * P1C + i1) * P2C * 512;

    for (int i2 = 0; i2 < P2C; i2++) {
        const float* c2 = c2g + (size_t)(t * P2C + i2) * 128;  // [r2][q2]
        __syncthreads();                 // previous iter's readers done
        if (tid < 128) {
            int qq = tid >> 5, rr = tid & 31;
            c2t[qq * 32 + rr] = c2[rr * 4 + qq];
        }
        __syncthreads();

        float a0 = 0.f, a1 = 0.f;
        const float4* c2v = (const float4*)(c2t + q2 * 32);
        #pragma unroll
        for (int k = 0; k < 8; k++) {
            float4 s  = c2v[k];
            float4 va = rowA[k];
            float4 vb = rowB[k];
            a0 = fmaf(va.x, s.x, a0); a0 = fmaf(va.y, s.y, a0);
            a0 = fmaf(va.z, s.z, a0); a0 = fmaf(va.w, s.w, a0);
            a1 = fmaf(vb.x, s.x, a1); a1 = fmaf(vb.y, s.y, a1);
            a1 = fmaf(vb.z, s.z, a1); a1 = fmaf(vb.w, s.w, a1);
        }
        float* o = Wt + i2 * 512;
        o[mA * 32 + r1]       = a0;     // m = mA
        o[(mA + 8) * 32 + r1] = a1;     // m = mA + 8
    }
}

// ---------------------------------------------------------------------------
// Kernel 2: per-bag lookup + pool.
// One warp per bag. Lane owns outputs j = lane (q0 = lane>>4) and j = lane+32
// (q0+2), m = lane & 15. out[q0][m] = sum_n sum_r1 c0[q0][r1] * W12[m][r1].
// W12 is m-major so each lane streams a contiguous 32-float r1-row (8x LDG.128).
// ---------------------------------------------------------------------------
__global__ void tt_lookup_kernel(const int* __restrict__ indices,
                                 const int* __restrict__ offsets,
                                 const float* __restrict__ c0g,
                                 float* __restrict__ out,
                                 int B, int bags_per_table) {
    int bag = (int)((blockIdx.x * (size_t)blockDim.x + threadIdx.x) >> 5);
    if (bag >= B) return;
    int lane = threadIdx.x & 31;
    int m    = lane & 15;
    int q0   = lane >> 4;               // 0 or 1; also q0+2

    int t = bag / bags_per_table;
    int s = offsets[bag], e = offsets[bag + 1];

    const float* c0tab = c0g + (size_t)t * P0 * 128;                 // [i0][q0][r1]
    const float* Wtab  = g_W12 + (size_t)t * P1C * P2C * 512;

    float a0 = 0.f, a1 = 0.f, b0 = 0.f, b1 = 0.f;   // split accumulators

    for (int p = s; p < e; p++) {
        int idx = indices[p];
        int i0  = idx / (P1C * P2C);
        int rem = idx - i0 * (P1C * P2C);
        int i1  = rem / P2C;
        int i2  = rem - i1 * P2C;

        const float4* w  = (const float4*)(Wtab + (size_t)(i1 * P2C + i2) * 512 + m * 32);
        const float4* ca = (const float4*)(c0tab + i0 * 128 + q0 * 32);
        const float4* cb = (const float4*)(c0tab + i0 * 128 + (q0 + 2) * 32);

        #pragma unroll
        for (int k = 0; k < 8; k++) {
            float4 wv = w[k];
            float4 av = ca[k];
            float4 bv = cb[k];
            a0 = fmaf(av.x, wv.x, a0); a1 = fmaf(av.y, wv.y, a1);
            a0 = fmaf(av.z, wv.z, a0); a1 = fmaf(av.w, wv.w, a1);
            b0 = fmaf(bv.x, wv.x, b0); b1 = fmaf(bv.y, wv.y, b1);
            b0 = fmaf(bv.z, wv.z, b0); b1 = fmaf(bv.w, wv.w, b1);
        }
    }

    out[(size_t)bag * DIM + lane]      = a0 + a1;
    out[(size_t)bag * DIM + 32 + lane] = b0 + b1;
}

// ---------------------------------------------------------------------------
// Launch. Inputs (metadata order): indices i32 (JAX default, no x64!),
// offsets i32, tt_core_0 f32, tt_core_1 f32, tt_core_2 f32. Output f32 [B,64].
// ---------------------------------------------------------------------------
extern "C" void kernel_launch(void* const* d_in, const int* in_sizes, int n_in,
                              void* d_out, int out_size) {
    const int* indices = (const int*)d_in[0];
    const int* offsets = (const int*)d_in[1];
    const float* c0 = (const float*)d_in[2];
    const float* c1 = (const float*)d_in[3];
    const float* c2 = (const float*)d_in[4];

    int B = in_sizes[1] - 1;
    int bags_per_table = B / NT;

    tt_precompute_kernel<<<NT * P1C, 256>>>(c1, c2);

    const int warps_per_block = 8;
    int blocks = (B + warps_per_block - 1) / warps_per_block;
    tt_lookup_kernel<<<blocks, warps_per_block * 32>>>(
        indices, offsets, c0, (float*)d_out, B, bags_per_table);
}

// round 3
// speedup vs baseline: 6.3558x; 6.3558x over previous
#include <cuda_runtime.h>
#include <stdint.h>

// TT config (fixed by the problem)
#define NT 4        // tables
#define P0 100
#define P1C 100
#define P2C 100

// Scratch: W12[t][i1][i2][m=q1*4+q2][r1]  (512 floats per (t,i1,i2) slice)
// 4 * 100 * 100 * 512 floats = 81.92 MB, static device global (no allocs).
__device__ float g_W12[(size_t)NT * P1C * P2C * 512];

// ---------------------------------------------------------------------------
// Kernel 1: precompute W12[m][r1] = sum_r2 c1[r1][q1][r2] * c2[r2][q2]
// One block per (t, i1). The thread's two c1 rows (64 floats) are hoisted into
// registers ONCE (they were being re-read, 32-lines-per-LDG, every i2 iter).
// Inner loop: smem-broadcast c2 + 64 FFMA + 2 coalesced STG.
// ---------------------------------------------------------------------------
__global__ void tt_precompute_kernel(const float* __restrict__ c1g,
                                     const float* __restrict__ c2g) {
    int b = blockIdx.x;                 // 0..399
    int t = b / P1C, i1 = b % P1C;
    const float* c1 = c1g + (size_t)(t * P1C + i1) * 4096;   // [r1][q1][r2]

    __shared__ __align__(16) float c2t[128];                 // [q2][r2] transposed

    int tid = threadIdx.x;              // 256 threads; warp id == mA
    int r1  = tid & 31;
    int mA  = tid >> 5;                 // 0..7 ; also handles mB = mA + 8
    int q1A = mA >> 2;                  // 0..1 ; q1B = q1A + 2
    int q2  = mA & 3;

    // Hoist c1 rows into registers (one-time uncoalesced cost).
    const float4* rowA = (const float4*)(c1 + (r1 * 4 + q1A) * 32);
    const float4* rowB = (const float4*)(c1 + (r1 * 4 + q1A + 2) * 32);
    float4 A[8], Bv[8];
    #pragma unroll
    for (int k = 0; k < 8; k++) { A[k] = rowA[k]; Bv[k] = rowB[k]; }

    float* Wt = g_W12 + (size_t)(t * P1C + i1) * P2C * 512;
    const float* c2base = c2g + (size_t)t * P2C * 128;       // [i2][r2][q2]

    for (int i2 = 0; i2 < P2C; i2++) {
        __syncthreads();                 // previous iter's c2t readers done
        if (tid < 128) {
            int qq = tid >> 5, rr = tid & 31;
            c2t[qq * 32 + rr] = c2base[i2 * 128 + rr * 4 + qq];
        }
        __syncthreads();

        float a0 = 0.f, a1 = 0.f;
        const float4* c2v = (const float4*)(c2t + q2 * 32);  // warp-uniform -> broadcast
        #pragma unroll
        for (int k = 0; k < 8; k++) {
            float4 s = c2v[k];
            a0 = fmaf(A[k].x,  s.x, a0); a0 = fmaf(A[k].y,  s.y, a0);
            a0 = fmaf(A[k].z,  s.z, a0); a0 = fmaf(A[k].w,  s.w, a0);
            a1 = fmaf(Bv[k].x, s.x, a1); a1 = fmaf(Bv[k].y, s.y, a1);
            a1 = fmaf(Bv[k].z, s.z, a1); a1 = fmaf(Bv[k].w, s.w, a1);
        }
        float* o = Wt + i2 * 512;
        o[mA * 32 + r1]       = a0;      // m = mA      (coalesced 128B per warp)
        o[(mA + 8) * 32 + r1] = a1;      // m = mA + 8
    }
}

// ---------------------------------------------------------------------------
// Kernel 2: per-bag lookup + pool. One warp per bag.
// The warp reads each 2KB W12 slice LINEARLY: lane l, round r reads float4 at
// float offset r*128 + 4l  ->  4 coalesced LDG.128 (nL=4 each) instead of the
// old 128-line-scatter. Lane owns (m = r*4 + l/8, r1 chunk = 4*(l%8)), keeps
// acc[r][q0]; group-of-8 shfl reduction once per bag.
// ---------------------------------------------------------------------------
__global__ void tt_lookup_kernel(const int* __restrict__ indices,
                                 const int* __restrict__ offsets,
                                 const float* __restrict__ c0g,
                                 float* __restrict__ out,
                                 int B, int bags_per_table) {
    int bag = (int)((blockIdx.x * (size_t)blockDim.x + threadIdx.x) >> 5);
    if (bag >= B) return;
    int l = threadIdx.x & 31;
    int j = l & 7;                      // r1-chunk id (floats 4j..4j+3)
    int g = l >> 3;                     // m-group (m = r*4 + g)

    int t = bag / bags_per_table;
    int s = offsets[bag], e = offsets[bag + 1];

    const float4* c0tab = (const float4*)(c0g + (size_t)t * P0 * 128);     // [i0][q0][r1]
    const float4* Wtab  = (const float4*)(g_W12 + (size_t)t * P1C * P2C * 512);

    float acc[4][4];                    // [r][q0]
    #pragma unroll
    for (int r = 0; r < 4; r++)
        #pragma unroll
        for (int q = 0; q < 4; q++) acc[r][q] = 0.f;

    for (int base = s; base < e; base += 32) {
        int n = min(32, e - base);
        int myidx = (base + l < e) ? indices[base + l] : 0;   // coalesced fetch
        for (int p = 0; p < n; p++) {
            int idx = __shfl_sync(0xffffffffu, myidx, p);
            int i0  = idx / (P1C * P2C);
            int rem = idx - i0 * (P1C * P2C);
            int i1  = rem / P2C;
            int i2  = rem - i1 * P2C;

            const float4* wb = Wtab + (size_t)(i1 * P2C + i2) * 128;
            const float4* cb = c0tab + i0 * 32;

            float4 cq[4];
            #pragma unroll
            for (int q = 0; q < 4; q++) cq[q] = cb[q * 8 + j];  // 1 line each

            #pragma unroll
            for (int r = 0; r < 4; r++) {
                float4 w = wb[r * 32 + l];                      // coalesced 512B
                #pragma unroll
                for (int q = 0; q < 4; q++) {
                    acc[r][q] = fmaf(cq[q].x, w.x, acc[r][q]);
                    acc[r][q] = fmaf(cq[q].y, w.y, acc[r][q]);
                    acc[r][q] = fmaf(cq[q].z, w.z, acc[r][q]);
                    acc[r][q] = fmaf(cq[q].w, w.w, acc[r][q]);
                }
            }
        }
    }

    // Reduce r1 partial sums across the 8 lanes of each m-group.
    #pragma unroll
    for (int r = 0; r < 4; r++)
        #pragma unroll
        for (int q = 0; q < 4; q++) {
            float v = acc[r][q];
            v += __shfl_xor_sync(0xffffffffu, v, 1);
            v += __shfl_xor_sync(0xffffffffu, v, 2);
            v += __shfl_xor_sync(0xffffffffu, v, 4);
            acc[r][q] = v;
        }

    // Each lane j of a group writes 2 of the group's 16 outputs.
    // out position for acc[r][q0] is q0*16 + r*4 + g.
    float* ob = out + (size_t)bag * 64;
    #pragma unroll
    for (int jj = 0; jj < 8; jj++) {
        if (j == jj) {
            const int ia = 2 * jj, ib = 2 * jj + 1;
            ob[(ia & 3) * 16 + (ia >> 2) * 4 + g] = acc[ia >> 2][ia & 3];
            ob[(ib & 3) * 16 + (ib >> 2) * 4 + g] = acc[ib >> 2][ib & 3];
        }
    }
}

// ---------------------------------------------------------------------------
// Launch. Inputs: indices i32, offsets i32, cores f32. Output f32 [B, 64].
// ---------------------------------------------------------------------------
extern "C" void kernel_launch(void* const* d_in, const int* in_sizes, int n_in,
                              void* d_out, int out_size) {
    const int* indices = (const int*)d_in[0];
    const int* offsets = (const int*)d_in[1];
    const float* c0 = (const float*)d_in[2];
    const float* c1 = (const float*)d_in[3];
    const float* c2 = (const float*)d_in[4];

    int B = in_sizes[1] - 1;
    int bags_per_table = B / NT;

    tt_precompute_kernel<<<NT * P1C, 256>>>(c1, c2);

    const int warps_per_block = 8;
    int blocks = (B + warps_per_block - 1) / warps_per_block;
    tt_lookup_kernel<<<blocks, warps_per_block * 32>>>(
        indices, offsets, c0, (float*)d_out, B, bags_per_table);
}

// round 4
// speedup vs baseline: 8.1027x; 1.2748x over previous
#include <cuda_runtime.h>
#include <cuda_fp16.h>
#include <stdint.h>

#define NT 4
#define P0 100
#define P1C 100
#define P2C 100

// Scratch: W12[t][i1][i2][m=q1*4+q2][r1] in fp16 (512 halves = 1KB per slice).
// 4*100*100*512 halves = 41 MB -> fully L2-resident.
__device__ __half g_W12[(size_t)NT * P1C * P2C * 512];

// ---- Blackwell packed fp32 helpers -----------------------------------------
#define FMA_F32X2(d, a, b, c) \
    asm("fma.rn.f32x2 %0, %1, %2, %3;" : "=l"(d) : "l"(a), "l"(b), "l"(c))
#define ADD_F32X2_(d, a, b) \
    asm("add.rn.f32x2 %0, %1, %2;" : "=l"(d) : "l"(a), "l"(b))

__device__ __forceinline__ unsigned long long pack2(float lo, float hi) {
    unsigned long long r;
    asm("mov.b64 %0, {%1, %2};" : "=l"(r) : "f"(lo), "f"(hi));
    return r;
}
__device__ __forceinline__ float2 unpack2(unsigned long long v) {
    float2 f;
    asm("mov.b64 {%0, %1}, %2;" : "=f"(f.x), "=f"(f.y) : "l"(v));
    return f;
}

// ---------------------------------------------------------------------------
// Kernel 1: W12[m][r1] = sum_r2 c1[r1][q1][r2] * c2[r2][q2], fp16 output.
// Grid 800 = (t, i1, i2-half). 512 threads: thread = (m=tid>>5, r1=tid&31).
// c1 row hoisted+packed into registers once; half c2 table transposed in smem
// once (no per-i2 barriers). Inner loop: 8 LDS.128 + 16 FFMA2 + 1 STG.16.
// ---------------------------------------------------------------------------
__global__ __launch_bounds__(512) void tt_precompute_kernel(
        const float* __restrict__ c1g, const float* __restrict__ c2g) {
    int b = blockIdx.x;                        // 0..799
    int t  = b / (P1C * 2);
    int rm = b - t * (P1C * 2);
    int i1 = rm >> 1;
    int i2lo = (rm & 1) * 50;

    __shared__ float c2t[50 * 4 * 32];         // [i2'][q2][r2], 25.6KB

    int tid = threadIdx.x;
    int r1 = tid & 31;
    int mA = tid >> 5;                          // 0..15 == m
    int q1 = mA >> 2, q2 = mA & 3;

    // Hoist this thread's c1 row (32 floats) and pack adjacent-r2 pairs.
    const float* c1 = c1g + (size_t)(t * P1C + i1) * 4096;   // [r1][q1][r2]
    const float4* row = (const float4*)(c1 + (r1 * 4 + q1) * 32);
    unsigned long long PA[16];
    #pragma unroll
    for (int k = 0; k < 8; k++) {
        float4 a = row[k];
        PA[2 * k]     = pack2(a.x, a.y);
        PA[2 * k + 1] = pack2(a.z, a.w);
    }

    // Fill smem with transposed c2 half-table: c2t[i2'][q2][r2] = c2[i2][r2][q2]
    const float* c2base = c2g + ((size_t)t * P2C + i2lo) * 128;
    for (int idx = tid; idx < 50 * 128; idx += 512) {
        int i2p = idx >> 7;
        int rr  = (idx >> 2) & 31;
        int qq  = idx & 3;
        c2t[(i2p * 4 + qq) * 32 + rr] = c2base[idx];
    }
    __syncthreads();

    __half* Wt = g_W12 + ((size_t)(t * P1C + i1) * P2C + i2lo) * 512;

    for (int i2p = 0; i2p < 50; i2p++) {
        const ulonglong2* sp = (const ulonglong2*)(c2t + (i2p * 4 + q2) * 32);
        unsigned long long ac0 = 0ULL, ac1 = 0ULL;   // two f32x2 chains
        #pragma unroll
        for (int k = 0; k < 8; k++) {
            ulonglong2 s = sp[k];                    // pairs (r2=4k,4k+1),(4k+2,4k+3)
            FMA_F32X2(ac0, PA[2 * k],     s.x, ac0);
            FMA_F32X2(ac1, PA[2 * k + 1], s.y, ac1);
        }
        float2 f0 = unpack2(ac0), f1 = unpack2(ac1);
        float v = (f0.x + f0.y) + (f1.x + f1.y);
        Wt[i2p * 512 + mA * 32 + r1] = __float2half_rn(v);
    }
}

// ---------------------------------------------------------------------------
// Kernel 2: per-bag lookup + pool. One warp per bag.
// Lane l: j2 = l&3 (r1 chunk of 8), mlow = l>>2; round r gives m = 8r+mlow.
// W slice (1KB fp16) read with 2 coalesced LDG.128/lane; c0 pairs load as
// ulonglong2 (free f32x2 packing); 32 FFMA2 per lookup.
// ---------------------------------------------------------------------------
__global__ void tt_lookup_kernel(const int* __restrict__ indices,
                                 const int* __restrict__ offsets,
                                 const float* __restrict__ c0g,
                                 float* __restrict__ out,
                                 int B, int bags_per_table) {
    int bag = (int)((blockIdx.x * (size_t)blockDim.x + threadIdx.x) >> 5);
    if (bag >= B) return;
    int l = threadIdx.x & 31;
    int j2   = l & 3;
    int mlow = l >> 2;

    int t = bag / bags_per_table;
    int s = offsets[bag], e = offsets[bag + 1];

    const float*  c0tab = c0g + (size_t)t * P0 * 128;            // [i0][q0][r1]
    const __half* Wtab  = g_W12 + (size_t)t * P1C * P2C * 512;

    unsigned long long acc[2][4];                                // f32x2 [r][q0]
    #pragma unroll
    for (int r = 0; r < 2; r++)
        #pragma unroll
        for (int q = 0; q < 4; q++) acc[r][q] = 0ULL;

    for (int base = s; base < e; base += 32) {
        int n = min(32, e - base);
        int myidx = (base + l < e) ? indices[base + l] : 0;      // coalesced
        for (int p = 0; p < n; p++) {
            int idx = __shfl_sync(0xffffffffu, myidx, p);
            int i0  = idx / (P1C * P2C);
            int rem = idx - i0 * (P1C * P2C);
            int i1  = rem / P2C;
            int i2  = rem - i1 * P2C;

            const uint4* wb = (const uint4*)(Wtab + (size_t)(i1 * P2C + i2) * 512);
            const ulonglong2* cb = (const ulonglong2*)(c0tab + i0 * 128);

            // c0 pairs for this lane's 8-wide r1 chunk, all 4 q0.
            ulonglong2 cp[4][2];
            #pragma unroll
            for (int q = 0; q < 4; q++) {
                cp[q][0] = cb[q * 8 + j2 * 2];       // r1 pairs (8j2,+1),(+2,+3)
                cp[q][1] = cb[q * 8 + j2 * 2 + 1];   // r1 pairs (+4,+5),(+6,+7)
            }

            #pragma unroll
            for (int r = 0; r < 2; r++) {
                uint4 u = wb[r * 32 + l];            // 8 halves, coalesced 512B
                const __half2* h = (const __half2*)&u;
                unsigned long long wp[4];
                #pragma unroll
                for (int i = 0; i < 4; i++) {
                    float2 f = __half22float2(h[i]);
                    wp[i] = pack2(f.x, f.y);
                }
                #pragma unroll
                for (int q = 0; q < 4; q++) {
                    FMA_F32X2(acc[r][q], wp[0], cp[q][0].x, acc[r][q]);
                    FMA_F32X2(acc[r][q], wp[1], cp[q][0].y, acc[r][q]);
                    FMA_F32X2(acc[r][q], wp[2], cp[q][1].x, acc[r][q]);
                    FMA_F32X2(acc[r][q], wp[3], cp[q][1].y, acc[r][q]);
                }
            }
        }
    }

    // Reduce r1 partials across the 4 lanes of each (mlow) group.
    #pragma unroll
    for (int r = 0; r < 2; r++)
        #pragma unroll
        for (int q = 0; q < 4; q++) {
            unsigned long long o;
            o = __shfl_xor_sync(0xffffffffu, acc[r][q], 1);
            ADD_F32X2_(acc[r][q], acc[r][q], o);
            o = __shfl_xor_sync(0xffffffffu, acc[r][q], 2);
            ADD_F32X2_(acc[r][q], acc[r][q], o);
        }

    // Lane writes q0 == j2 for both r: out[bag][q0*16 + m], m = 8r + mlow.
    float* ob = out + (size_t)bag * 64;
    #pragma unroll
    for (int q = 0; q < 4; q++) {
        if (q == j2) {
            float2 f0 = unpack2(acc[0][q]);
            float2 f1 = unpack2(acc[1][q]);
            ob[q * 16 + mlow]     = f0.x + f0.y;
            ob[q * 16 + 8 + mlow] = f1.x + f1.y;
        }
    }
}

// ---------------------------------------------------------------------------
extern "C" void kernel_launch(void* const* d_in, const int* in_sizes, int n_in,
                              void* d_out, int out_size) {
    const int* indices = (const int*)d_in[0];
    const int* offsets = (const int*)d_in[1];
    const float* c0 = (const float*)d_in[2];
    const float* c1 = (const float*)d_in[3];
    const float* c2 = (const float*)d_in[4];

    int B = in_sizes[1] - 1;
    int bags_per_table = B / NT;

    tt_precompute_kernel<<<NT * P1C * 2, 512>>>(c1, c2);

    const int warps_per_block = 8;
    int blocks = (B + warps_per_block - 1) / warps_per_block;
    tt_lookup_kernel<<<blocks, warps_per_block * 32>>>(
        indices, offsets, c0, (float*)d_out, B, bags_per_table);
}